// round 3
// baseline (speedup 1.0000x reference)
#include <cuda_runtime.h>

#define NV 16384
#define CC 512
#define KK 64
#define BB 64
#define ROWS (BB * CC)          // one (batch, constraint) row per 8-thread group
#define TPR 8                   // threads per row
#define LPT 8                   // elements per thread (KK / TPR)
#define N_ITER 25
#define N_BISECT 18
#define BUDGETF 8.0f

// Persistent ADMM state (device globals: no allocation inside kernel_launch).
// g_lam is only *read* from iteration >=1, and iteration 0 overwrites it from
// the lam=0 initial condition, so graph replays are deterministic.
__device__ float g_lam[ROWS * KK];
__device__ float g_msg[2][ROWS * KK];   // ping-pong msg = z - lam

__device__ __forceinline__ float rsum(float v) {       // sum over 8-lane group
    v += __shfl_xor_sync(0xffffffffu, v, 1);
    v += __shfl_xor_sync(0xffffffffu, v, 2);
    v += __shfl_xor_sync(0xffffffffu, v, 4);
    return v;
}
__device__ __forceinline__ float rmin(float v) {
    v = fminf(v, __shfl_xor_sync(0xffffffffu, v, 1));
    v = fminf(v, __shfl_xor_sync(0xffffffffu, v, 2));
    v = fminf(v, __shfl_xor_sync(0xffffffffu, v, 4));
    return v;
}
__device__ __forceinline__ float rmax(float v) {
    v = fmaxf(v, __shfl_xor_sync(0xffffffffu, v, 1));
    v = fmaxf(v, __shfl_xor_sync(0xffffffffu, v, 2));
    v = fmaxf(v, __shfl_xor_sync(0xffffffffu, v, 4));
    return v;
}

template <bool FIRST>
__global__ void __launch_bounds__(256) admm_iter(const float* __restrict__ scores, int p)
{
    const int t = blockIdx.x * 256 + threadIdx.x;
    const int row = t >> 3;          // b*512 + c
    const int g = t & 7;             // eighth-row index, k in [8g, 8g+8)
    const int b = row >> 9;
    const int c = row & 511;

    const float* __restrict__ src = g_msg[p];
    float* __restrict__ dst = g_msg[p ^ 1];

    // scores: n = (32c + 8g + j) mod NV, 8 contiguous floats (32B aligned)
    const int base_n = ((c << 5) + (g << 3)) & (NV - 1);
    const float4* __restrict__ sc = (const float4*)(scores + b * NV + base_n);

    // own msg slice + lam slice
    const size_t rbase = (size_t)row * KK + (g << 3);
    const float4* __restrict__ mc = (const float4*)(src + rbase);
    const float4* __restrict__ lamv = (const float4*)(g_lam + rbase);

    // neighbor msg slice:
    //   g<4 : constraint c-1, offset k+32 = 8g+32
    //   g>=4: constraint c+1, offset k-32 = 8(g-4)
    const int cn = (g < 4) ? ((c - 1) & 511) : ((c + 1) & 511);
    const int kn = (g < 4) ? ((g << 3) + 32) : ((g - 4) << 3);
    const float4* __restrict__ mn4 = (const float4*)(src + ((size_t)((b << 9) + cn)) * KK + kn);

    float a[LPT];

    // ---- a[k] = clip((scores + t)/2, 0, 1) + lam ----
#pragma unroll
    for (int q = 0; q < 2; q++) {
        float4 sv = sc[q];
        float tx = sv.x, ty = sv.y, tz = sv.z, tw = sv.w;
        float lx = 0.f, ly = 0.f, lz = 0.f, lw = 0.f;
        if (!FIRST) {
            float4 m0 = mc[q];
            float4 m1 = mn4[q];
            float4 lv = lamv[q];
            tx += m0.x + m1.x; ty += m0.y + m1.y; tz += m0.z + m1.z; tw += m0.w + m1.w;
            lx = lv.x; ly = lv.y; lz = lv.z; lw = lv.w;
        }
        a[4 * q + 0] = __saturatef(tx * 0.5f) + lx;
        a[4 * q + 1] = __saturatef(ty * 0.5f) + ly;
        a[4 * q + 2] = __saturatef(tz * 0.5f) + lz;
        a[4 * q + 3] = __saturatef(tw * 0.5f) + lw;
    }

    // ---- feasibility: sum(clip(a,0,1)) <= budget ----
    float s0 = 0.f, s1 = 0.f, s2 = 0.f, s3 = 0.f;
#pragma unroll
    for (int k = 0; k < LPT; k += 4) {
        s0 += __saturatef(a[k]);
        s1 += __saturatef(a[k + 1]);
        s2 += __saturatef(a[k + 2]);
        s3 += __saturatef(a[k + 3]);
    }
    const float feas_sum = rsum((s0 + s1) + (s2 + s3));
    const bool feas = feas_sum <= BUDGETF;

    // ---- bisection bounds over the full 64-row: lo = min-1, hi = max ----
    float mn = fminf(fminf(a[0], a[1]), fminf(a[2], a[3]));
    float mx = fmaxf(fmaxf(a[0], a[1]), fmaxf(a[2], a[3]));
    mn = fminf(mn, fminf(fminf(a[4], a[5]), fminf(a[6], a[7])));
    mx = fmaxf(mx, fmaxf(fmaxf(a[4], a[5]), fmaxf(a[6], a[7])));
    float lo = rmin(mn) - 1.0f;
    float hi = rmax(mx);

    // ---- bisection (skipped only if all 4 rows in warp feasible) ----
    if (!__all_sync(0xffffffffu, feas)) {
#pragma unroll 1
        for (int it = 0; it < N_BISECT; ++it) {
            const float mid = 0.5f * (lo + hi);
            float t0 = 0.f, t1 = 0.f, t2 = 0.f, t3 = 0.f;
#pragma unroll
            for (int k = 0; k < LPT; k += 4) {
                t0 += __saturatef(a[k] - mid);
                t1 += __saturatef(a[k + 1] - mid);
                t2 += __saturatef(a[k + 2] - mid);
                t3 += __saturatef(a[k + 3] - mid);
            }
            const float s = rsum((t0 + t1) + (t2 + t3));   // same in all 8 lanes
            if (s > BUDGETF) lo = mid; else hi = mid;
        }
    }
    const float tau0 = 0.5f * (lo + hi);

    // ---- Newton correction on the active set (matches reference) ----
    float na = 0.f, gs = 0.f;
#pragma unroll
    for (int k = 0; k < LPT; k++) {
        const float d = a[k] - tau0;
        na += (d > 0.f && d < 1.f) ? 1.f : 0.f;
        gs += __saturatef(d);
    }
    const float nact = fmaxf(rsum(na), 1.0f);
    const float g_res = rsum(gs) - BUDGETF;
    const float tau = tau0 + g_res / nact;

    // ---- z = proj, lam' = a - z, msg' = z - lam' = 2z - a ----
    float4* __restrict__ lamo = (float4*)(g_lam + rbase);
    float4* __restrict__ msgo = (float4*)(dst + rbase);
#pragma unroll
    for (int q = 0; q < 2; q++) {
        float ln[4], mg[4];
#pragma unroll
        for (int j = 0; j < 4; j++) {
            const float ak = a[4 * q + j];
            const float zz = feas ? __saturatef(ak) : __saturatef(ak - tau);
            ln[j] = ak - zz;
            mg[j] = zz - ln[j];
        }
        lamo[q] = make_float4(ln[0], ln[1], ln[2], ln[3]);
        msgo[q] = make_float4(mg[0], mg[1], mg[2], mg[3]);
    }
}

// Final u_update: u[b,n] = clip((scores + msg[c0,k0] + msg[c0-1,k0+32]) / 2, 0, 1)
__global__ void __launch_bounds__(256) finalize_u(const float* __restrict__ scores,
                                                 float* __restrict__ out, int p)
{
    const int i = blockIdx.x * 256 + threadIdx.x;   // b*NV + n
    const float* __restrict__ msg = g_msg[p];
    const int b = i >> 14;
    const int n = i & (NV - 1);
    const int c0 = n >> 5;
    const int k0 = n & 31;
    const int c1 = (c0 - 1) & 511;
    const size_t base = (size_t)(b << 9);
    const float t = msg[(base + c0) * KK + k0] + msg[(base + c1) * KK + k0 + 32];
    out[i] = __saturatef((scores[i] + t) * 0.5f);
}

extern "C" void kernel_launch(void* const* d_in, const int* in_sizes, int n_in,
                              void* d_out, int out_size)
{
    const float* scores = (const float*)d_in[0];
    if (n_in > 1 && in_sizes[0] == CC * KK) scores = (const float*)d_in[1];
    float* out = (float*)d_out;

    admm_iter<true><<<ROWS * TPR / 256, 256>>>(scores, 0);
    for (int it = 1; it < N_ITER; ++it)
        admm_iter<false><<<ROWS * TPR / 256, 256>>>(scores, it & 1);
    // iteration `it` writes g_msg[(it&1)^1]; last (it=24) wrote g_msg[1]
    finalize_u<<<(BB * NV) / 256, 256>>>(scores, out, 1);
}

// round 5
// speedup vs baseline: 1.1820x; 1.1820x over previous
#include <cuda_runtime.h>

#define NV 16384
#define CC 512
#define KK 64
#define BB 64
#define ROWS (BB * CC)          // one (batch, constraint) row per 4-thread group
#define TPR 4
#define LPT 16                  // elements per thread
#define N_ITER 25
#define N_QUAD 9                // 9 quadrisection rounds == 18 bisections (validated width)
#define BUDGETF 8.0f

// Persistent ADMM state (device globals: no allocation inside kernel_launch).
// g_lam is only *read* from iteration >=1, and iteration 0 overwrites it from
// the lam=0 initial condition, so graph replays are deterministic.
__device__ float g_lam[ROWS * KK];
__device__ float g_msg[2][ROWS * KK];   // ping-pong msg = z - lam

__device__ __forceinline__ float qsum(float v) {       // sum over 4-lane group
    v += __shfl_xor_sync(0xffffffffu, v, 1);
    v += __shfl_xor_sync(0xffffffffu, v, 2);
    return v;
}
__device__ __forceinline__ float qmin(float v) {
    v = fminf(v, __shfl_xor_sync(0xffffffffu, v, 1));
    v = fminf(v, __shfl_xor_sync(0xffffffffu, v, 2));
    return v;
}
__device__ __forceinline__ float qmax(float v) {
    v = fmaxf(v, __shfl_xor_sync(0xffffffffu, v, 1));
    v = fmaxf(v, __shfl_xor_sync(0xffffffffu, v, 2));
    return v;
}

template <bool FIRST>
__global__ void __launch_bounds__(256) admm_iter(const float* __restrict__ scores, int p)
{
    const int t = blockIdx.x * 256 + threadIdx.x;
    const int row = t >> 2;          // b*512 + c
    const int g = t & 3;             // quarter-row index, k in [16g, 16g+16)
    const int b = row >> 9;
    const int c = row & 511;

    const float* __restrict__ src = g_msg[p];
    float* __restrict__ dst = g_msg[p ^ 1];

    // scores: n = (32c + 16g + j) mod NV, 16 contiguous (chunk never crosses wrap)
    const int base_n = ((c << 5) + (g << 4)) & (NV - 1);
    const float4* __restrict__ sc = (const float4*)(scores + b * NV + base_n);

    // own msg slice + lam slice
    const size_t rbase = (size_t)row * KK + (g << 4);
    const float4* __restrict__ mc = (const float4*)(src + rbase);
    const float4* __restrict__ lamv = (const float4*)(g_lam + rbase);

    // neighbor msg slice:
    //   g<2 : constraint c-1, offset k+32 = 16g+32
    //   g>=2: constraint c+1, offset k-32 = 16(g-2)
    const int cn = (g < 2) ? ((c - 1) & 511) : ((c + 1) & 511);
    const int kn = (g < 2) ? ((g << 4) + 32) : ((g - 2) << 4);
    const float4* __restrict__ mn4 = (const float4*)(src + ((size_t)((b << 9) + cn)) * KK + kn);

    float a[LPT];

    // ---- a[k] = clip((scores + t)/2, 0, 1) + lam ----
#pragma unroll
    for (int q = 0; q < 4; q++) {
        float4 sv = sc[q];
        float tx = sv.x, ty = sv.y, tz = sv.z, tw = sv.w;
        float lx = 0.f, ly = 0.f, lz = 0.f, lw = 0.f;
        if (!FIRST) {
            float4 m0 = mc[q];
            float4 m1 = mn4[q];
            float4 lv = lamv[q];
            tx += m0.x + m1.x; ty += m0.y + m1.y; tz += m0.z + m1.z; tw += m0.w + m1.w;
            lx = lv.x; ly = lv.y; lz = lv.z; lw = lv.w;
        }
        a[4 * q + 0] = __saturatef(tx * 0.5f) + lx;
        a[4 * q + 1] = __saturatef(ty * 0.5f) + ly;
        a[4 * q + 2] = __saturatef(tz * 0.5f) + lz;
        a[4 * q + 3] = __saturatef(tw * 0.5f) + lw;
    }

    // ---- feasibility: sum(clip(a,0,1)) <= budget ----
    float s0 = 0.f, s1 = 0.f, s2 = 0.f, s3 = 0.f;
#pragma unroll
    for (int k = 0; k < LPT; k += 4) {
        s0 += __saturatef(a[k]);
        s1 += __saturatef(a[k + 1]);
        s2 += __saturatef(a[k + 2]);
        s3 += __saturatef(a[k + 3]);
    }
    const bool feas = qsum((s0 + s1) + (s2 + s3)) <= BUDGETF;

    float tau = 0.f;

    if (!__all_sync(0xffffffffu, feas)) {
        // ---- bracket: lo = min(a)-1 (s=64 there), hi = max(a) (s=0 there) ----
        float mn = fminf(fminf(a[0], a[1]), fminf(a[2], a[3]));
        float mx = fmaxf(fmaxf(a[0], a[1]), fmaxf(a[2], a[3]));
#pragma unroll
        for (int k = 4; k < LPT; k += 4) {
            mn = fminf(mn, fminf(fminf(a[k], a[k + 1]), fminf(a[k + 2], a[k + 3])));
            mx = fmaxf(mx, fmaxf(fmaxf(a[k], a[k + 1]), fmaxf(a[k + 2], a[k + 3])));
        }
        float lo = qmin(mn) - 1.0f;
        float hi = qmax(mx);

        // ---- quadrisection: 9 rounds, each shrinks the bracket 4x.
        // Final width = W0/2^18 — identical to 18 bisections (validated),
        // but the serial dependence chain is only 9 rounds; the 3 interior
        // evaluations per round are independent (ILP + interleaved shuffles).
#pragma unroll 1
        for (int it = 0; it < N_QUAD; ++it) {
            const float W = hi - lo;
            const float m1 = fmaf(0.25f, W, lo);
            const float m2 = fmaf(0.50f, W, lo);
            const float m3 = fmaf(0.75f, W, lo);
            float p0 = 0.f, p1 = 0.f, p2 = 0.f, p3 = 0.f;   // s(m1)
            float q0 = 0.f, q1 = 0.f, q2 = 0.f, q3 = 0.f;   // s(m2)
            float r0 = 0.f, r1 = 0.f, r2 = 0.f, r3 = 0.f;   // s(m3)
#pragma unroll
            for (int k = 0; k < LPT; k += 4) {
                p0 += __saturatef(a[k] - m1);
                p1 += __saturatef(a[k + 1] - m1);
                p2 += __saturatef(a[k + 2] - m1);
                p3 += __saturatef(a[k + 3] - m1);
                q0 += __saturatef(a[k] - m2);
                q1 += __saturatef(a[k + 1] - m2);
                q2 += __saturatef(a[k + 2] - m2);
                q3 += __saturatef(a[k + 3] - m2);
                r0 += __saturatef(a[k] - m3);
                r1 += __saturatef(a[k + 1] - m3);
                r2 += __saturatef(a[k + 2] - m3);
                r3 += __saturatef(a[k + 3] - m3);
            }
            const float sm1 = qsum((p0 + p1) + (p2 + p3));   // group-uniform
            const float sm2 = qsum((q0 + q1) + (q2 + q3));
            const float sm3 = qsum((r0 + r1) + (r2 + r3));
            const bool g1 = sm1 > BUDGETF;   // root right of m1
            const bool g2 = sm2 > BUDGETF;
            const bool g3 = sm3 > BUDGETF;
            lo = g3 ? m3 : (g2 ? m2 : (g1 ? m1 : lo));
            hi = g1 ? (g2 ? (g3 ? hi : m3) : m2) : m1;
        }
        const float tau0 = 0.5f * (lo + hi);

        // ---- Newton correction on the active set (matches reference) ----
        float na = 0.f, gs = 0.f;
#pragma unroll
        for (int k = 0; k < LPT; k++) {
            const float d = a[k] - tau0;
            na += (d > 0.f && d < 1.f) ? 1.f : 0.f;
            gs += __saturatef(d);
        }
        const float nact = fmaxf(qsum(na), 1.0f);
        const float g_res = qsum(gs) - BUDGETF;
        tau = tau0 + g_res / nact;
    }

    // ---- z = proj, lam' = a - z, msg' = z - lam' = 2z - a ----
    float4* __restrict__ lamo = (float4*)(g_lam + rbase);
    float4* __restrict__ msgo = (float4*)(dst + rbase);
#pragma unroll
    for (int q = 0; q < 4; q++) {
        float ln[4], mg[4];
#pragma unroll
        for (int j = 0; j < 4; j++) {
            const float ak = a[4 * q + j];
            const float zz = feas ? __saturatef(ak) : __saturatef(ak - tau);
            ln[j] = ak - zz;
            mg[j] = zz - ln[j];
        }
        lamo[q] = make_float4(ln[0], ln[1], ln[2], ln[3]);
        msgo[q] = make_float4(mg[0], mg[1], mg[2], mg[3]);
    }
}

// Final u_update: u[b,n] = clip((scores + msg[c0,k0] + msg[c0-1,k0+32]) / 2, 0, 1)
__global__ void __launch_bounds__(256) finalize_u(const float* __restrict__ scores,
                                                 float* __restrict__ out, int p)
{
    const int i = blockIdx.x * 256 + threadIdx.x;   // b*NV + n
    const float* __restrict__ msg = g_msg[p];
    const int b = i >> 14;
    const int n = i & (NV - 1);
    const int c0 = n >> 5;
    const int k0 = n & 31;
    const int c1 = (c0 - 1) & 511;
    const size_t base = (size_t)(b << 9);
    const float t = msg[(base + c0) * KK + k0] + msg[(base + c1) * KK + k0 + 32];
    out[i] = __saturatef((scores[i] + t) * 0.5f);
}

extern "C" void kernel_launch(void* const* d_in, const int* in_sizes, int n_in,
                              void* d_out, int out_size)
{
    const float* scores = (const float*)d_in[0];
    if (n_in > 1 && in_sizes[0] == CC * KK) scores = (const float*)d_in[1];
    float* out = (float*)d_out;

    admm_iter<true><<<ROWS * TPR / 256, 256>>>(scores, 0);
    for (int it = 1; it < N_ITER; ++it)
        admm_iter<false><<<ROWS * TPR / 256, 256>>>(scores, it & 1);
    // iteration `it` writes g_msg[(it&1)^1]; last (it=24) wrote g_msg[1]
    finalize_u<<<(BB * NV) / 256, 256>>>(scores, out, 1);
}

// round 6
// speedup vs baseline: 1.5179x; 1.2842x over previous
#include <cuda_runtime.h>

#define NV 16384
#define CC 512
#define KK 64
#define BB 64
#define N_ROWS 80               // 8 halo + 64 valid + 8 halo
#define HALO 8
#define SMS 68                  // smem row stride in floats (bank-conflict pad)
#define N_QUAD 9                // == 18 bisections (validated accuracy)
#define BUDGETF 8.0f

// Double-buffered global state: blocks read parity p, write p^1, so halo
// reads never race with neighbor-block writes within a launch.
__device__ float g_msg[2][BB * CC * KK];
__device__ float g_lam[2][BB * CC * KK];

__device__ __forceinline__ float qsum(float v) {
    v += __shfl_xor_sync(0xffffffffu, v, 1);
    v += __shfl_xor_sync(0xffffffffu, v, 2);
    return v;
}
__device__ __forceinline__ float qmin(float v) {
    v = fminf(v, __shfl_xor_sync(0xffffffffu, v, 1));
    v = fminf(v, __shfl_xor_sync(0xffffffffu, v, 2));
    return v;
}
__device__ __forceinline__ float qmax(float v) {
    v = fmaxf(v, __shfl_xor_sync(0xffffffffu, v, 1));
    v = fmaxf(v, __shfl_xor_sync(0xffffffffu, v, 2));
    return v;
}

// One block: batch b, constraints [c0, c0+64) valid, rows [c0-8, c0+72) held.
// Runs T fused ADMM iterations; msg ping-pongs in smem, lam/scores in regs.
template <bool FIRST>
__global__ void __launch_bounds__(320, 3) fused_admm(const float* __restrict__ scores,
                                                     int p, int T)
{
    __shared__ float s_msg[2][N_ROWS][SMS];

    const int t = threadIdx.x;
    const int r = t >> 2;                 // local row 0..79
    const int g = t & 3;                  // quarter-row, k in [16g,16g+16)
    const int b = blockIdx.x >> 3;
    const int c0 = (blockIdx.x & 7) << 6;
    const int c = (c0 - HALO + r) & (CC - 1);
    const int grow = ((b << 9) + c) * KK + (g << 4);   // global row-slice offset

    // ---- scores into registers (window is 16-aligned, never straddles NV) ----
    float sc[16];
    {
        const int nb = ((c << 5) + (g << 4)) & (NV - 1);
        const float4* sp = (const float4*)(scores + b * NV + nb);
#pragma unroll
        for (int q = 0; q < 4; q++) {
            float4 v = sp[q];
            sc[4 * q] = v.x; sc[4 * q + 1] = v.y; sc[4 * q + 2] = v.z; sc[4 * q + 3] = v.w;
        }
    }

    // ---- lam into registers, msg into smem buffer 0 ----
    float lam[16];
    if (FIRST) {
#pragma unroll
        for (int k = 0; k < 16; k++) lam[k] = 0.f;
        float4* d = (float4*)&s_msg[0][r][g << 4];
#pragma unroll
        for (int q = 0; q < 4; q++) d[q] = make_float4(0.f, 0.f, 0.f, 0.f);
    } else {
        const float4* lp = (const float4*)(g_lam[p] + grow);
        const float4* mp = (const float4*)(g_msg[p] + grow);
        float4* d = (float4*)&s_msg[0][r][g << 4];
#pragma unroll
        for (int q = 0; q < 4; q++) {
            float4 lv = lp[q];
            lam[4 * q] = lv.x; lam[4 * q + 1] = lv.y; lam[4 * q + 2] = lv.z; lam[4 * q + 3] = lv.w;
            d[q] = mp[q];
        }
    }
    __syncthreads();

    // neighbor row (clamped; clamped rows are halo-garbage and never written back)
    const int rn = (g < 2) ? ((r > 0) ? r - 1 : 0) : ((r < N_ROWS - 1) ? r + 1 : N_ROWS - 1);
    const int kn = (g < 2) ? ((g << 4) + 32) : ((g - 2) << 4);

    for (int it = 0; it < T; ++it) {
        const int sb = it & 1;
        const float4* mo = (const float4*)&s_msg[sb][r][g << 4];
        const float4* mn = (const float4*)&s_msg[sb][rn][kn];

        float a[16];
#pragma unroll
        for (int q = 0; q < 4; q++) {
            float4 o = mo[q];
            float4 n = mn[q];
            a[4 * q + 0] = __saturatef((sc[4 * q + 0] + o.x + n.x) * 0.5f) + lam[4 * q + 0];
            a[4 * q + 1] = __saturatef((sc[4 * q + 1] + o.y + n.y) * 0.5f) + lam[4 * q + 1];
            a[4 * q + 2] = __saturatef((sc[4 * q + 2] + o.z + n.z) * 0.5f) + lam[4 * q + 2];
            a[4 * q + 3] = __saturatef((sc[4 * q + 3] + o.w + n.w) * 0.5f) + lam[4 * q + 3];
        }

        // feasibility
        float f0 = 0.f, f1 = 0.f;
#pragma unroll
        for (int k = 0; k < 16; k += 2) { f0 += __saturatef(a[k]); f1 += __saturatef(a[k + 1]); }
        const bool feas = qsum(f0 + f1) <= BUDGETF;

        float tau = 0.f;
        if (!__all_sync(0xffffffffu, feas)) {
            float mn1 = fminf(a[0], a[1]), mx1 = fmaxf(a[0], a[1]);
#pragma unroll
            for (int k = 2; k < 16; k += 2) {
                mn1 = fminf(mn1, fminf(a[k], a[k + 1]));
                mx1 = fmaxf(mx1, fmaxf(a[k], a[k + 1]));
            }
            float lo = qmin(mn1) - 1.0f;
            float hi = qmax(mx1);

#pragma unroll 1
            for (int qq = 0; qq < N_QUAD; ++qq) {
                const float W = hi - lo;
                const float m1 = fmaf(0.25f, W, lo);
                const float m2 = fmaf(0.50f, W, lo);
                const float m3 = fmaf(0.75f, W, lo);
                float p0 = 0.f, p1 = 0.f, q0 = 0.f, q1 = 0.f, r0 = 0.f, r1 = 0.f;
#pragma unroll
                for (int k = 0; k < 16; k += 2) {
                    p0 += __saturatef(a[k] - m1); p1 += __saturatef(a[k + 1] - m1);
                    q0 += __saturatef(a[k] - m2); q1 += __saturatef(a[k + 1] - m2);
                    r0 += __saturatef(a[k] - m3); r1 += __saturatef(a[k + 1] - m3);
                }
                const bool g1 = qsum(p0 + p1) > BUDGETF;
                const bool g2 = qsum(q0 + q1) > BUDGETF;
                const bool g3 = qsum(r0 + r1) > BUDGETF;
                lo = g3 ? m3 : (g2 ? m2 : (g1 ? m1 : lo));
                hi = g1 ? (g2 ? (g3 ? hi : m3) : m2) : m1;
            }
            const float tau0 = 0.5f * (lo + hi);

            // Newton polish on the active set (matches reference)
            float na = 0.f, gs = 0.f;
#pragma unroll
            for (int k = 0; k < 16; k++) {
                const float d = a[k] - tau0;
                na += (d > 0.f && d < 1.f) ? 1.f : 0.f;
                gs += __saturatef(d);
            }
            const float nact = fmaxf(qsum(na), 1.0f);
            tau = tau0 + (qsum(gs) - BUDGETF) / nact;
        }

        // z, lam' = a - z, msg' = 2z - a
        float4* dst = (float4*)&s_msg[sb ^ 1][r][g << 4];
#pragma unroll
        for (int q = 0; q < 4; q++) {
            float mg[4];
#pragma unroll
            for (int j = 0; j < 4; j++) {
                const float ak = a[4 * q + j];
                const float zz = feas ? __saturatef(ak) : __saturatef(ak - tau);
                lam[4 * q + j] = ak - zz;
                mg[j] = zz - (ak - zz);
            }
            dst[q] = make_float4(mg[0], mg[1], mg[2], mg[3]);
        }
        __syncthreads();
    }

    // ---- write back valid rows only ----
    if (r >= HALO && r < HALO + 64) {
        const int fb = T & 1;
        float4* gm = (float4*)(g_msg[p ^ 1] + grow);
        float4* gl = (float4*)(g_lam[p ^ 1] + grow);
        const float4* sm = (const float4*)&s_msg[fb][r][g << 4];
#pragma unroll
        for (int q = 0; q < 4; q++) {
            gm[q] = sm[q];
            gl[q] = make_float4(lam[4 * q], lam[4 * q + 1], lam[4 * q + 2], lam[4 * q + 3]);
        }
    }
}

// Final u_update: u[b,n] = clip((scores + msg[c0,k0] + msg[c0-1,k0+32]) / 2, 0, 1)
__global__ void __launch_bounds__(256) finalize_u(const float* __restrict__ scores,
                                                  float* __restrict__ out, int p)
{
    const int i = blockIdx.x * 256 + threadIdx.x;   // b*NV + n
    const float* __restrict__ msg = g_msg[p];
    const int b = i >> 14;
    const int n = i & (NV - 1);
    const int c0 = n >> 5;
    const int k0 = n & 31;
    const int c1 = (c0 - 1) & 511;
    const int base = b << 9;
    const float t = msg[(base + c0) * KK + k0] + msg[(base + c1) * KK + k0 + 32];
    out[i] = __saturatef((scores[i] + t) * 0.5f);
}

extern "C" void kernel_launch(void* const* d_in, const int* in_sizes, int n_in,
                              void* d_out, int out_size)
{
    const float* scores = (const float*)d_in[0];
    if (n_in > 1 && in_sizes[0] == CC * KK) scores = (const float*)d_in[1];
    float* out = (float*)d_out;

    // 25 iterations = 8 + 8 + 8 + 1, halo width 8 per launch
    fused_admm<true ><<<512, 320>>>(scores, 0, 8);   // writes parity 1
    fused_admm<false><<<512, 320>>>(scores, 1, 8);   // writes parity 0
    fused_admm<false><<<512, 320>>>(scores, 0, 8);   // writes parity 1
    fused_admm<false><<<512, 320>>>(scores, 1, 1);   // writes parity 0
    finalize_u<<<(BB * NV) / 256, 256>>>(scores, out, 0);
}